// round 12
// baseline (speedup 1.0000x reference)
#include <cuda_runtime.h>
#include <cuda_fp16.h>
#include <stdint.h>

// MessageFunction via mma.sync m16n8k16 fp16 (fp32 accum), persistent CTAs.
// R12: 48 rows/warp (TILE=384) cuts W2 B-fragment smem bytes per edge by 1.5x
//      (the measured L1 roofline). 16-col GEMM2 chunks keep regs <=128 for
//      2 CTAs/SM. Warp-private single-buffer cp.async pipeline (R11), padded
//      E/H strides, scalar red scatter.

#define TPB   256
#define TILE  384
#define ESTR  20
#define HSTR  20

// ---- smem float offsets (per CTA 96448 bytes) ----
#define OF_W2F 0       // 8192 fl: W2 B-frags uint2[ks(4)][ntg(32)][lane(32)]
#define OF_W1F 8192    // 512 fl : W1 B-frags uint2[nt(8)][lane(32)]
#define OF_B1  8704    // 64
#define OF_B2  8768    // 256
#define OF_E   9024    // 7680 fl : e tile f32 [384][stride 20]
#define OF_H   16704   // 7680 fl : h tile f32 [384][stride 20]
#define SMEM_FLOATS 24384   // 97536 bytes (x2 CTAs = 195072 <= 228KB/SM)

__device__ __forceinline__ uint32_t pack_h2(float a, float b) {
    __half2 h = __floats2half2_rn(a, b);
    return *(uint32_t*)&h;
}
__device__ __forceinline__ uint32_t smem_u32(const void* p) {
    uint32_t a;
    asm("{ .reg .u64 t; cvta.to.shared.u64 t, %1; cvt.u32.u64 %0, t; }" : "=r"(a) : "l"(p));
    return a;
}

// Not volatile: pure register computation; let ptxas pipeline it.
#define MMA_F16(d, a, b0, b1) \
    asm("mma.sync.aligned.m16n8k16.row.col.f32.f16.f16.f32 " \
        "{%0,%1,%2,%3}, {%4,%5,%6,%7}, {%8,%9}, {%0,%1,%2,%3};" \
        : "+f"((d)[0]), "+f"((d)[1]), "+f"((d)[2]), "+f"((d)[3]) \
        : "r"((a)[0]), "r"((a)[1]), "r"((a)[2]), "r"((a)[3]), \
          "r"(b0), "r"(b1))

__device__ __forceinline__ void red_add(float* p, float v) {
    asm volatile("red.global.add.f32 [%0], %1;" :: "l"(p), "f"(v) : "memory");
}
__device__ __forceinline__ void cp16(uint32_t s, const void* g) {
    asm volatile("cp.async.cg.shared.global [%0], [%1], 16;" :: "r"(s), "l"(g));
}
__device__ __forceinline__ void cp_commit() {
    asm volatile("cp.async.commit_group;" ::: "memory");
}
__device__ __forceinline__ void cp_wait_all() {
    asm volatile("cp.async.wait_group 0;" ::: "memory");
}

extern "C" __global__ void __launch_bounds__(TPB, 2)
msg_mma_kernel(const int* __restrict__ index_v,
               const float* __restrict__ h_w,
               const float* __restrict__ e_vw,
               const float* __restrict__ W1,
               const float* __restrict__ b1,
               const float* __restrict__ W2,
               const float* __restrict__ b2,
               float* __restrict__ out,
               int n_edge) {
    extern __shared__ float sm[];
    const uint32_t sb = smem_u32(sm);
    const int tid  = threadIdx.x;
    const int warp = tid >> 5;
    const int lane = tid & 31;
    const int q = lane & 3;       // quad col
    const int g = lane >> 2;      // group row

    // ================= stage weight fragments (once per CTA) =================
    for (int s = tid; s < 4096; s += TPB) {
        int ks = s >> 10, rest = s & 1023, ntg = rest >> 5, ln = rest & 31;
        int qq = ln & 3, gg = ln >> 2;
        int n = ntg * 8 + gg, r0 = ks * 16 + 2 * qq;
        uint2 b;
        b.x = pack_h2(W2[(r0)     * 256 + n], W2[(r0 + 1) * 256 + n]);
        b.y = pack_h2(W2[(r0 + 8) * 256 + n], W2[(r0 + 9) * 256 + n]);
        ((uint2*)(sm + OF_W2F))[s] = b;
    }
    for (int s = tid; s < 256; s += TPB) {
        int nt = s >> 5, ln = s & 31;
        int qq = ln & 3, gg = ln >> 2;
        int n = nt * 8 + gg;
        uint2 b;
        b.x = pack_h2(W1[(2 * qq)     * 64 + n], W1[(2 * qq + 1) * 64 + n]);
        b.y = pack_h2(W1[(2 * qq + 8) * 64 + n], W1[(2 * qq + 9) * 64 + n]);
        ((uint2*)(sm + OF_W1F))[s] = b;
    }
    if (tid < 64)  sm[OF_B1 + tid] = b1[tid];
    if (tid < 256) sm[OF_B2 + tid] = b2[tid];

    const int ntiles = (n_edge + TILE - 1) / TILE;

    // ---- async stage of tile t: warp stages its own 48 rows ----
    // lane stages row warp*48+lane; lanes 0..15 also row warp*48+32+lane.
    auto stage = [&](int t) {
        const int base = t * TILE;
        const int rem  = n_edge - base;
        {
            const int r = warp * 48 + lane;
            const int sr = r < rem ? r : rem - 1;
            const char* ep = (const char*)(e_vw + (size_t)(base + sr) * 16);
            const char* hp = (const char*)(h_w  + (size_t)(base + sr) * 16);
            const uint32_t de = sb + (OF_E + r * ESTR) * 4;
            const uint32_t dh = sb + (OF_H + r * HSTR) * 4;
#pragma unroll
            for (int i = 0; i < 4; i++) {
                cp16(de + 16 * i, ep + 16 * i);
                cp16(dh + 16 * i, hp + 16 * i);
            }
        }
        if (lane < 16) {
            const int r = warp * 48 + 32 + lane;
            const int sr = r < rem ? r : rem - 1;
            const char* ep = (const char*)(e_vw + (size_t)(base + sr) * 16);
            const char* hp = (const char*)(h_w  + (size_t)(base + sr) * 16);
            const uint32_t de = sb + (OF_E + r * ESTR) * 4;
            const uint32_t dh = sb + (OF_H + r * HSTR) * 4;
#pragma unroll
            for (int i = 0; i < 4; i++) {
                cp16(de + 16 * i, ep + 16 * i);
                cp16(dh + 16 * i, hp + 16 * i);
            }
        }
        cp_commit();
    };

    __syncthreads();   // weights visible CTA-wide (E/H are warp-private)

    // ---- prologue ----
    if (blockIdx.x < ntiles) stage(blockIdx.x);

    for (int t = blockIdx.x; t < ntiles; t += gridDim.x) {
        const int base = t * TILE;

        cp_wait_all();     // this warp's rows landed
        __syncwarp();      // cross-lane smem visibility within the warp

        // ---- GEMM1 in three 16-row passes; build A-frags ha[3][4][4] ----
        uint32_t ha[3][4][4];
#pragma unroll
        for (int p = 0; p < 3; p++) {
            const int r0 = warp * 48 + p * 16 + g;
            const float* Er = sm + OF_E + r0 * ESTR;
            uint32_t ea[4];
            {
                float2 c0 = *(const float2*)(Er + 2 * q);
                float2 c1 = *(const float2*)(Er + 8 * ESTR + 2 * q);
                float2 c2 = *(const float2*)(Er + 8 + 2 * q);
                float2 c3 = *(const float2*)(Er + 8 * ESTR + 8 + 2 * q);
                ea[0] = pack_h2(c0.x, c0.y);
                ea[1] = pack_h2(c1.x, c1.y);
                ea[2] = pack_h2(c2.x, c2.y);
                ea[3] = pack_h2(c3.x, c3.y);
            }
            float acc1[8][4];
#pragma unroll
            for (int nt = 0; nt < 8; nt++)
#pragma unroll
                for (int r = 0; r < 4; r++) acc1[nt][r] = 0.0f;
#pragma unroll
            for (int nt = 0; nt < 8; nt++) {
                uint2 b = ((const uint2*)(sm + OF_W1F))[nt * 32 + lane];
                MMA_F16(acc1[nt], ea, b.x, b.y);
            }
#pragma unroll
            for (int nt = 0; nt < 8; nt++) {
                float2 bb = *(const float2*)(sm + OF_B1 + nt * 8 + 2 * q);
                float v0 = fmaxf(acc1[nt][0] + bb.x, 0.0f);
                float v1 = fmaxf(acc1[nt][1] + bb.y, 0.0f);
                float v2 = fmaxf(acc1[nt][2] + bb.x, 0.0f);
                float v3 = fmaxf(acc1[nt][3] + bb.y, 0.0f);
                int ks = nt >> 1, hi = (nt & 1) * 2;
                ha[p][ks][hi]     = pack_h2(v0, v1);   // row g
                ha[p][ks][hi + 1] = pack_h2(v2, v3);   // row g+8
            }
        }

        // ---- h regs + nodes (warp-private rows) ----
        float hreg[3][2][4];
        int   node[3][2];
        bool  vld[3][2];
#pragma unroll
        for (int mt = 0; mt < 3; mt++)
#pragma unroll
            for (int rr = 0; rr < 2; rr++) {
                const int row = warp * 48 + mt * 16 + g + rr * 8;
                const float* Hr = sm + OF_H + row * HSTR;
                float2 h0 = *(const float2*)(Hr + 2 * q);
                float2 h1 = *(const float2*)(Hr + 8 + 2 * q);
                hreg[mt][rr][0] = h0.x; hreg[mt][rr][1] = h0.y;
                hreg[mt][rr][2] = h1.x; hreg[mt][rr][3] = h1.y;
                const int ge = base + row;
                vld[mt][rr]  = ge < n_edge;
                node[mt][rr] = vld[mt][rr] ? __ldg(index_v + ge) : 0;
            }

        // ---- all E/H reads done for this warp: stage next tile now ----
        __syncwarp();
        const int tn = t + gridDim.x;
        if (tn < ntiles) stage(tn);

        // ---- GEMM2 + epilogue, 16 chunks of 16 cols (chunk c = output m=c) ----
#pragma unroll
        for (int c = 0; c < 16; c++) {
            float acc[3][2][4];
#pragma unroll
            for (int mt = 0; mt < 3; mt++)
#pragma unroll
                for (int nt = 0; nt < 2; nt++)
#pragma unroll
                    for (int r = 0; r < 4; r++) acc[mt][nt][r] = 0.0f;
#pragma unroll
            for (int ks = 0; ks < 4; ks++)
#pragma unroll
                for (int nt = 0; nt < 2; nt++) {
                    uint2 b = ((const uint2*)(sm + OF_W2F))[(ks * 32 + c * 2 + nt) * 32 + lane];
                    MMA_F16(acc[0][nt], ha[0][ks], b.x, b.y);
                    MMA_F16(acc[1][nt], ha[1][ks], b.x, b.y);
                    MMA_F16(acc[2][nt], ha[2][ks], b.x, b.y);
                }
            float pacc[3][2];
#pragma unroll
            for (int mt = 0; mt < 3; mt++) { pacc[mt][0] = 0.0f; pacc[mt][1] = 0.0f; }
#pragma unroll
            for (int nt = 0; nt < 2; nt++) {
                float2 bb = *(const float2*)(sm + OF_B2 + c * 16 + nt * 8 + 2 * q);
                const int hb = nt * 2;
#pragma unroll
                for (int mt = 0; mt < 3; mt++) {
                    pacc[mt][0] = fmaf(acc[mt][nt][0] + bb.x, hreg[mt][0][hb],     pacc[mt][0]);
                    pacc[mt][0] = fmaf(acc[mt][nt][1] + bb.y, hreg[mt][0][hb + 1], pacc[mt][0]);
                    pacc[mt][1] = fmaf(acc[mt][nt][2] + bb.x, hreg[mt][1][hb],     pacc[mt][1]);
                    pacc[mt][1] = fmaf(acc[mt][nt][3] + bb.y, hreg[mt][1][hb + 1], pacc[mt][1]);
                }
            }
#pragma unroll
            for (int mt = 0; mt < 3; mt++)
#pragma unroll
                for (int rr = 0; rr < 2; rr++) {
                    float v = pacc[mt][rr];
                    v += __shfl_xor_sync(0xFFFFFFFFu, v, 1);
                    v += __shfl_xor_sync(0xFFFFFFFFu, v, 2);
                    if (q == 0 && vld[mt][rr])
                        red_add(out + (size_t)node[mt][rr] * 16 + c, v);
                }
        }
        // no __syncthreads: E/H rows are warp-private; pipeline is per-warp
    }
}

// ---------------- launch ----------------
extern "C" void kernel_launch(void* const* d_in, const int* in_sizes, int n_in,
                              void* d_out, int out_size) {
    const int*   index_v = nullptr;
    const float* h_w = nullptr;
    const float* e_vw = nullptr;
    const float* W1 = nullptr;
    const float* b1 = nullptr;
    const float* W2 = nullptr;
    const float* b2 = nullptr;

    int big_idx[8]; long long big_sz[8]; int nb = 0;
    for (int i = 0; i < n_in; i++) {
        long long s = in_sizes[i];
        if (s == 1024)       W1 = (const float*)d_in[i];
        else if (s == 64)    b1 = (const float*)d_in[i];
        else if (s == 16384) W2 = (const float*)d_in[i];
        else if (s == 256)   b2 = (const float*)d_in[i];
        else if (s > 100000 && nb < 8) { big_idx[nb] = i; big_sz[nb] = s; nb++; }
    }
    long long min_sz = big_sz[0]; int min_pos = 0;
    for (int i = 1; i < nb; i++)
        if (big_sz[i] < min_sz) { min_sz = big_sz[i]; min_pos = i; }
    index_v = (const int*)d_in[big_idx[min_pos]];
    int n_edge = (int)min_sz;
    bool got_h = false;
    for (int i = 0; i < nb; i++) {
        if (i == min_pos) continue;
        if (!got_h) { h_w = (const float*)d_in[big_idx[i]]; got_h = true; }
        else        { e_vw = (const float*)d_in[big_idx[i]]; }
    }

    float* out = (float*)d_out;
    cudaMemsetAsync(out, 0, (size_t)out_size * sizeof(float));

    static bool attr_set = false;
    if (!attr_set) {
        cudaFuncSetAttribute(msg_mma_kernel,
                             cudaFuncAttributeMaxDynamicSharedMemorySize,
                             SMEM_FLOATS * (int)sizeof(float));
        attr_set = true;
    }
    int ntiles = (n_edge + TILE - 1) / TILE;
    int grid = ntiles < 304 ? ntiles : 304;   // 2 CTAs/SM x 152 SMs
    msg_mma_kernel<<<grid, TPB, SMEM_FLOATS * sizeof(float)>>>(
        index_v, h_w, e_vw, W1, b1, W2, b2, out, n_edge);
}